// round 4
// baseline (speedup 1.0000x reference)
#include <cuda_runtime.h>
#include <cuda_bf16.h>

// ---------------------------------------------------------------------------
// LGNInputLayerCell: i_in[post] += weights[s] * (inputs_t[pre[s]] > 0)
// inputs (metadata order):
//   d_in[0] : int32  inputs_t   [N_SOURCE]      (17400)
//   d_in[1] : int32  indices    [N_SYN, 2]      (post, pre) interleaved
//   d_in[2] : float  weights    [N_SYN]
//   d_in[3] : int32  n_post     [1]             (unused; out_size == n_post)
// output: float [n_post]
// ---------------------------------------------------------------------------

// Active-source bitmask scratch. 65536 words = 2M sources capacity
// (N_SOURCE = 17400 -> 544 words used, 2.2 KB -> L1-resident everywhere).
__device__ unsigned int g_active_mask[65536];

__global__ void build_mask_kernel(const int* __restrict__ inputs_t,
                                  int n_source, int n_words) {
    int w = blockIdx.x * blockDim.x + threadIdx.x;
    if (w >= n_words) return;
    unsigned int m = 0u;
    int base = w << 5;
    int lim = n_source - base;
    if (lim > 32) lim = 32;
    #pragma unroll 4
    for (int b = 0; b < lim; ++b) {
        if (inputs_t[base + b] > 0) m |= (1u << b);
    }
    g_active_mask[w] = m;
}

__global__ void zero_out_kernel(float* __restrict__ out, int n) {
    int i = blockIdx.x * blockDim.x + threadIdx.x;
    if (i < n) out[i] = 0.0f;
}

// Main scatter-reduce. One thread handles one *pair* of synapses:
// a single coalesced int4 (two (post,pre) records) + one float2.
// Inactive synapses are exactly zero contributions -> skip the atomic.
__global__ void seg_sum_kernel(const int4* __restrict__ idx4,
                               const float2* __restrict__ w2,
                               float* __restrict__ out,
                               int pairs) {
    int i = blockIdx.x * blockDim.x + threadIdx.x;
    if (i >= pairs) return;
    int4   p = __ldg(&idx4[i]);   // (post0, pre0, post1, pre1)
    float2 w = __ldg(&w2[i]);

    unsigned int m0 = g_active_mask[((unsigned)p.y) >> 5];
    unsigned int m1 = g_active_mask[((unsigned)p.w) >> 5];

    if ((m0 >> (p.y & 31)) & 1u) atomicAdd(out + p.x, w.x);
    if ((m1 >> (p.w & 31)) & 1u) atomicAdd(out + p.z, w.y);
}

// Tail (odd N_SYN; N_SYN = 30M is even, but stay general).
__global__ void seg_sum_tail_kernel(const int2* __restrict__ idx2,
                                    const float* __restrict__ wts,
                                    float* __restrict__ out,
                                    int start, int n_syn) {
    int i = start + blockIdx.x * blockDim.x + threadIdx.x;
    if (i >= n_syn) return;
    int2 p = __ldg(&idx2[i]);     // (post, pre)
    unsigned int m = g_active_mask[((unsigned)p.y) >> 5];
    if ((m >> (p.y & 31)) & 1u) atomicAdd(out + p.x, __ldg(&wts[i]));
}

extern "C" void kernel_launch(void* const* d_in, const int* in_sizes, int n_in,
                              void* d_out, int out_size) {
    const int*   inputs_t = (const int*)d_in[0];
    const int*   indices  = (const int*)d_in[1];
    const float* weights  = (const float*)d_in[2];
    float*       out      = (float*)d_out;

    const int n_source = in_sizes[0];
    const int n_syn    = in_sizes[2];
    const int n_post   = out_size;

    // 1) build active-source bitmask
    const int n_words = (n_source + 31) >> 5;
    build_mask_kernel<<<(n_words + 127) / 128, 128>>>(inputs_t, n_source, n_words);

    // 2) zero the (0xAA-poisoned) output
    zero_out_kernel<<<(n_post + 255) / 256, 256>>>(out, n_post);

    // 3) scatter-reduce, two synapses per thread (coalesced int4/float2 loads)
    const int pairs = n_syn >> 1;
    if (pairs > 0) {
        seg_sum_kernel<<<(pairs + 255) / 256, 256>>>(
            (const int4*)indices, (const float2*)weights, out, pairs);
    }
    const int done = pairs << 1;
    if (done < n_syn) {
        seg_sum_tail_kernel<<<1, 256>>>(
            (const int2*)indices, weights, out, done, n_syn);
    }
}

// round 5
// speedup vs baseline: 1.2689x; 1.2689x over previous
#include <cuda_runtime.h>
#include <cuda_bf16.h>

// ---------------------------------------------------------------------------
// LGNInputLayerCell: i_in[post] += weights[s] * (inputs_t[pre[s]] > 0)
// inputs (metadata order):
//   d_in[0] : int32  inputs_t   [N_SOURCE]      (17400)
//   d_in[1] : int32  indices    [N_SYN, 2]      (post, pre) interleaved
//   d_in[2] : float  weights    [N_SYN]
//   d_in[3] : int32  n_post     (unused; out_size == n_post)
// output: float [n_post]
// ---------------------------------------------------------------------------

// Active-source bitmask scratch (global, built by prologue).
// 2048 words = 65536 sources capacity (N_SOURCE = 17400 -> 544 words used).
#define MASK_WORDS_MAX 2048
__device__ unsigned int g_active_mask[MASK_WORDS_MAX];

// ---------------------------------------------------------------------------
// Prologue: build the active bitmask (ballot, 1 thread / source) AND zero the
// 0xAA-poisoned output. One kernel => per-replay launch sequence is
// [prologue, seg_sum], so ncu -s 5 -c 1 lands on seg_sum.
// ---------------------------------------------------------------------------
__global__ void prologue_kernel(const int* __restrict__ inputs_t,
                                int n_source,
                                float* __restrict__ out, int n_post) {
    const int i = blockIdx.x * blockDim.x + threadIdx.x;

    // --- bitmask build: whole warps inside/outside (round-up-32 bound) ---
    const int n_src32 = (n_source + 31) & ~31;
    if (i < n_src32) {
        int v = (i < n_source) ? inputs_t[i] : 0;
        unsigned int b = __ballot_sync(0xffffffffu, v > 0);
        if ((threadIdx.x & 31) == 0) g_active_mask[i >> 5] = b;
    }

    // --- zero output, 4 floats per thread ---
    const int base = i << 2;
    if (base + 3 < n_post) {
        *reinterpret_cast<float4*>(out + base) = make_float4(0.f, 0.f, 0.f, 0.f);
    } else if (base < n_post) {
        for (int j = base; j < n_post; ++j) out[j] = 0.0f;
    }
}

// ---------------------------------------------------------------------------
// Main scatter-reduce. 4 synapses per thread:
//   2x int4  (four (post,pre) records, coalesced)
//   1x float4 (four weights, coalesced)
// Active mask is staged in SMEM (random lookups over ~544 words -> LDS with
// mild bank conflicts instead of L1tex scattered-gather replays).
// Inactive synapses contribute exactly 0.0 -> skip the atomic entirely.
// ---------------------------------------------------------------------------
__global__ __launch_bounds__(256)
void seg_sum_kernel(const int4* __restrict__ idx4,
                    const float4* __restrict__ w4,
                    float* __restrict__ out,
                    int quads, int n_words) {
    __shared__ unsigned int s_mask[MASK_WORDS_MAX];

    // vectorized copy of the mask into SMEM (n_words <= 2048 guaranteed by host)
    {
        const int n_w4 = (n_words + 3) >> 2;
        int4* s4 = reinterpret_cast<int4*>(s_mask);
        const int4* g4 = reinterpret_cast<const int4*>(g_active_mask);
        for (int w = threadIdx.x; w < n_w4; w += blockDim.x) s4[w] = g4[w];
    }
    __syncthreads();

    const int i = blockIdx.x * blockDim.x + threadIdx.x;
    if (i >= quads) return;

    // front-batch the three streaming loads (independent -> MLP 3)
    int4   a = __ldg(&idx4[2 * i]);       // (post0, pre0, post1, pre1)
    int4   b = __ldg(&idx4[2 * i + 1]);   // (post2, pre2, post3, pre3)
    float4 w = __ldg(&w4[i]);

    const unsigned int m0 = s_mask[((unsigned)a.y) >> 5];
    const unsigned int m1 = s_mask[((unsigned)a.w) >> 5];
    const unsigned int m2 = s_mask[((unsigned)b.y) >> 5];
    const unsigned int m3 = s_mask[((unsigned)b.w) >> 5];

    if ((m0 >> (a.y & 31)) & 1u) atomicAdd(out + a.x, w.x);
    if ((m1 >> (a.w & 31)) & 1u) atomicAdd(out + a.z, w.y);
    if ((m2 >> (b.y & 31)) & 1u) atomicAdd(out + b.x, w.z);
    if ((m3 >> (b.w & 31)) & 1u) atomicAdd(out + b.z, w.w);
}

// Tail for n_syn % 4 (N_SYN = 30M -> empty, but stay general).
__global__ void seg_sum_tail_kernel(const int2* __restrict__ idx2,
                                    const float* __restrict__ wts,
                                    float* __restrict__ out,
                                    int start, int n_syn) {
    int i = start + blockIdx.x * blockDim.x + threadIdx.x;
    if (i >= n_syn) return;
    int2 p = __ldg(&idx2[i]);     // (post, pre)
    unsigned int m = g_active_mask[((unsigned)p.y) >> 5];
    if ((m >> (p.y & 31)) & 1u) atomicAdd(out + p.x, __ldg(&wts[i]));
}

extern "C" void kernel_launch(void* const* d_in, const int* in_sizes, int n_in,
                              void* d_out, int out_size) {
    const int*   inputs_t = (const int*)d_in[0];
    const int*   indices  = (const int*)d_in[1];
    const float* weights  = (const float*)d_in[2];
    float*       out      = (float*)d_out;

    const int n_source = in_sizes[0];
    const int n_syn    = in_sizes[2];
    const int n_post   = out_size;

    // 1) fused prologue: bitmask + output zeroing
    {
        const int n_src32   = (n_source + 31) & ~31;
        const int n_zero_th = (n_post + 3) >> 2;
        const int n_thr     = (n_src32 > n_zero_th) ? n_src32 : n_zero_th;
        prologue_kernel<<<(n_thr + 255) / 256, 256>>>(inputs_t, n_source, out, n_post);
    }

    // 2) scatter-reduce: 4 synapses per thread (SMEM-staged mask)
    const int n_words = (n_source + 31) >> 5;   // 544 for N_SOURCE=17400 (<2048)
    const int quads   = n_syn >> 2;
    if (quads > 0) {
        seg_sum_kernel<<<(quads + 255) / 256, 256>>>(
            (const int4*)indices, (const float4*)weights, out, quads, n_words);
    }
    const int done = quads << 2;
    if (done < n_syn) {
        seg_sum_tail_kernel<<<1, 256>>>(
            (const int2*)indices, weights, out, done, n_syn);
    }
}